// round 11
// baseline (speedup 1.0000x reference)
#include <cuda_runtime.h>
#include <cuda_bf16.h>
#include <math.h>

#define NB 8
#define ND 60
#define NP 1024
#define NK 20
#define NT (NP*NK)
#define SLOPE 0.2f

typedef unsigned long long ull;

// ---------------- device scratch ----------------
static __device__ float dg_pd[NB*NP*NP];
static __device__ float dg_xx[NB*NP];
static __device__ int   dg_idx[NB*NP*NK];
static __device__ float dg_P[NB*64*NP];
static __device__ float dg_S[NB*64*NP];
static __device__ float dg_h1[NB*64*NT];
static __device__ float dg_h2[NB*64*NT];
static __device__ float dg_h3[NB*128*NT];
static __device__ float dg_z [NB*512*NP];
static __device__ float dg_o5[NB*256*NP];
static __device__ float dg_o6[NB*1024*NP];
static __device__ double dg_sum[6][1024];
static __device__ double dg_ssq[6][1024];
static __device__ float dg_scZ[512], dg_shZ[512];
static __device__ float dg_sc5[256], dg_sh5[256];
static __device__ float dg_sc6[1024], dg_sh6[1024];
// pre-transposed weights Wt[k][m]
static __device__ float dg_w2t[64*64];
static __device__ float dg_w3t[64*128];
static __device__ float dg_w5t[512*256];
static __device__ float dg_w6t[256*1024];
// bf16-split W4 [m][k] for mma.sync conv4
static __device__ __nv_bfloat16 dg_w4h[256*128], dg_w4l[256*128];

// packed fp32x2 FMA (sm_103a) — exact fp32 numerics per lane, 2x rate
#define FMA2(d, a, bb) asm("fma.rn.f32x2 %0, %1, %2, %0;" : "+l"(d) : "l"(a), "l"(bb))
#define DUP2(d, f)     asm("mov.b64 %0, {%1, %1};" : "=l"(d) : "f"(f))
#define UNPK2(lo, hi, d) asm("mov.b64 {%0, %1}, %2;" : "=f"(lo), "=f"(hi) : "l"(d))

#define LRELU4(v, s, h)                                           \
    v.x = fmaf(v.x, s, h); v.x = v.x >= 0.f ? v.x : SLOPE*v.x;    \
    v.y = fmaf(v.y, s, h); v.y = v.y >= 0.f ? v.y : SLOPE*v.y;    \
    v.z = fmaf(v.z, s, h); v.z = v.z >= 0.f ? v.z : SLOPE*v.z;    \
    v.w = fmaf(v.w, s, h); v.w = v.w >= 0.f ? v.w : SLOPE*v.w;

// cp.async helpers (sm_80+ baseline PTX — valid on plain compute_103)
#define CPA16(dst_u32, gptr) \
    asm volatile("cp.async.ca.shared.global [%0], [%1], 16;" :: "r"(dst_u32), "l"(gptr) : "memory")
#define CPA_COMMIT() asm volatile("cp.async.commit_group;" ::: "memory")
#define CPA_WAIT0()  asm volatile("cp.async.wait_group 0;" ::: "memory")
#define CPA_WAIT1()  asm volatile("cp.async.wait_group 1;" ::: "memory")

// legacy bf16 tensor-core mma (sm_80 baseline PTX)
#define MMA_BF16(c, a0, a1, a2, a3, b0, b1) \
    asm volatile("mma.sync.aligned.m16n8k16.row.col.f32.bf16.bf16.f32 " \
        "{%0,%1,%2,%3}, {%4,%5,%6,%7}, {%8,%9}, {%0,%1,%2,%3};" \
        : "+f"((c)[0]), "+f"((c)[1]), "+f"((c)[2]), "+f"((c)[3]) \
        : "r"(a0), "r"(a1), "r"(a2), "r"(a3), "r"(b0), "r"(b1))

static __device__ __forceinline__ unsigned smem_u32(const void* p) {
    unsigned a;
    asm("{ .reg .u64 t; cvta.to.shared.u64 t, %1; cvt.u32.u64 %0, t; }" : "=r"(a) : "l"(p));
    return a;
}

// ---------------- small kernels ----------------

__global__ void k_zero() {
    int i = blockIdx.x*1024 + threadIdx.x;
    ((double*)dg_sum)[i] = 0.0;
    ((double*)dg_ssq)[i] = 0.0;
}

// w[m][k] -> wt[k][m]; dims multiples of 32
__global__ void k_wt(const float* __restrict__ w, float* __restrict__ wt, int M, int K) {
    __shared__ float t[32][33];
    int k0 = blockIdx.x*32, m0 = blockIdx.y*32;
    int tx = threadIdx.x, ty = threadIdx.y;
    t[ty][tx] = w[(size_t)(m0+ty)*K + k0 + tx];
    __syncthreads();
    wt[(size_t)(k0+ty)*M + m0 + tx] = t[tx][ty];
}

__global__ void k_wsplit(const float* __restrict__ w, __nv_bfloat16* __restrict__ hi,
                         __nv_bfloat16* __restrict__ lo, int n) {
    int i = blockIdx.x*256 + threadIdx.x;
    if (i < n) {
        float v = w[i];
        __nv_bfloat16 h = __float2bfloat16(v);
        hi[i] = h;
        lo[i] = __float2bfloat16(v - __bfloat162float(h));
    }
}

__global__ void k_xx(const float* __restrict__ x) {
    int b = blockIdx.x, n = threadIdx.x;
    float s = 0.f;
    #pragma unroll
    for (int d = 0; d < ND; d++) {
        float v = x[((size_t)b*ND + d)*NP + n];
        s = fmaf(v, v, s);
    }
    dg_xx[b*NP + n] = s;
}

// pd[b,n,m] = 2*dot(x_n,x_m) - xx_n - xx_m
__global__ void __launch_bounds__(128) k_pdist(const float* __restrict__ x) {
    __shared__ float sn[ND][32], sm[ND][32];
    int b = blockIdx.z;
    int n0 = blockIdx.y*32, m0 = blockIdx.x*32;
    int tx = threadIdx.x, ty = threadIdx.y;
    int tid = ty*8 + tx;
    for (int e = tid; e < ND*32; e += 128) {
        int d = e >> 5, c = e & 31;
        size_t base = ((size_t)b*ND + d)*NP;
        sn[d][c] = x[base + n0 + c];
        sm[d][c] = x[base + m0 + c];
    }
    __syncthreads();
    ull acc[2][2] = {{0ull,0ull},{0ull,0ull}};
    #pragma unroll
    for (int d = 0; d < ND; d++) {
        ull sn2 = *(const ull*)&sn[d][ty*2];
        float nlo, nhi; UNPK2(nlo, nhi, sn2);
        ull dlo, dhi; DUP2(dlo, nlo); DUP2(dhi, nhi);
        ull mp0 = *(const ull*)&sm[d][tx*4];
        ull mp1 = *(const ull*)&sm[d][tx*4+2];
        FMA2(acc[0][0], mp0, dlo); FMA2(acc[0][1], mp1, dlo);
        FMA2(acc[1][0], mp0, dhi); FMA2(acc[1][1], mp1, dhi);
    }
    float xm[4];
    #pragma unroll
    for (int j = 0; j < 4; j++) xm[j] = dg_xx[b*NP + m0 + tx*4 + j];
    #pragma unroll
    for (int i = 0; i < 2; i++) {
        int n = n0 + ty*2 + i;
        float xn = dg_xx[b*NP + n];
        float v0, v1, v2, v3;
        UNPK2(v0, v1, acc[i][0]);
        UNPK2(v2, v3, acc[i][1]);
        float4 o = make_float4(2.f*v0 - xn - xm[0], 2.f*v1 - xn - xm[1],
                               2.f*v2 - xn - xm[2], 2.f*v3 - xn - xm[3]);
        *(float4*)(dg_pd + ((size_t)b*NP + n)*NP + m0 + tx*4) = o;
    }
}

// warp-per-row top-20 via per-lane bitonic sort of packed (value,idx) keys
__global__ void k_topk() {
    int warp = threadIdx.x >> 5, lane = threadIdx.x & 31;
    int row = blockIdx.x*8 + warp;
    const float* rp = dg_pd + (size_t)row*NP;
    ull k[32];
    #pragma unroll
    for (int i = 0; i < 8; i++) {
        float4 t = *(const float4*)(rp + i*128 + lane*4);
        float vv[4] = {t.x, t.y, t.z, t.w};
        #pragma unroll
        for (int j = 0; j < 4; j++) {
            unsigned fb = __float_as_uint(vv[j]);
            unsigned u = (fb & 0x80000000u) ? ~fb : (fb | 0x80000000u);
            unsigned idx = (unsigned)(i*128 + lane*4 + j);
            k[i*4+j] = ((ull)u << 32) | (ull)(0xFFFFFFFFu - idx);
        }
    }
    #pragma unroll
    for (int sz = 2; sz <= 32; sz <<= 1) {
        #pragma unroll
        for (int st = sz >> 1; st > 0; st >>= 1) {
            #pragma unroll
            for (int i = 0; i < 32; i++) {
                int j = i ^ st;
                if (j > i) {
                    bool sw = ((i & sz) == 0) ? (k[i] < k[j]) : (k[i] > k[j]);
                    if (sw) { ull t = k[i]; k[i] = k[j]; k[j] = t; }
                }
            }
        }
    }
    int* outp = dg_idx + (size_t)row*NK;
    #pragma unroll
    for (int t = 0; t < NK; t++) {
        ull best = k[0];
        #pragma unroll
        for (int d = 16; d; d >>= 1) {
            ull o = __shfl_xor_sync(0xffffffffu, best, d);
            if (o > best) best = o;
        }
        if (lane == 0) outp[t] = (int)(0xFFFFFFFFu - (unsigned)(best & 0xFFFFFFFFull));
        if (k[0] == best) {
            #pragma unroll
            for (int j = 0; j < 20; j++) k[j] = k[j+1];
        }
    }
}

__global__ void k_ps(const float* __restrict__ x, const float* __restrict__ w1) {
    __shared__ float wa[ND], ws[ND];
    int o = blockIdx.y, b = blockIdx.z, tid = threadIdx.x;
    if (tid < ND) {
        float a = w1[o*120 + tid];
        wa[tid] = a;
        ws[tid] = w1[o*120 + 60 + tid] - a;
    }
    __syncthreads();
    int n = blockIdx.x*256 + tid;
    float p = 0.f, s = 0.f;
    #pragma unroll
    for (int d = 0; d < ND; d++) {
        float xv = x[((size_t)b*ND + d)*NP + n];
        p = fmaf(wa[d], xv, p);
        s = fmaf(ws[d], xv, s);
    }
    dg_P[((size_t)b*64 + o)*NP + n] = p;
    dg_S[((size_t)b*64 + o)*NP + n] = s;
}

__global__ void k_h1(const float* __restrict__ b1) {
    int tid = threadIdx.x;
    int n = blockIdx.x*256 + tid;
    int o = blockIdx.y, b = blockIdx.z;
    float sv = dg_S[((size_t)b*64 + o)*NP + n] + b1[o];
    const float* Pb = dg_P + ((size_t)b*64 + o)*NP;
    const int* ip = dg_idx + ((size_t)b*NP + n)*NK;
    float vals[NK];
    float sum = 0.f, ss = 0.f, mx = -INFINITY;
    #pragma unroll
    for (int j = 0; j < NK; j++) {
        float v = Pb[ip[j]] + sv;
        vals[j] = v;
        sum += v;
        ss = fmaf(v, v, ss);
        mx = fmaxf(mx, v);
    }
    float* dst = dg_h1 + (((size_t)b*64 + o)*NP + n)*NK;
    #pragma unroll
    for (int j4 = 0; j4 < 5; j4++)
        ((float4*)dst)[j4] = make_float4(vals[4*j4], vals[4*j4+1], vals[4*j4+2], vals[4*j4+3]);
    dg_z[((size_t)b*512 + o)*NP + n] = mx;

    #pragma unroll
    for (int d = 1; d < 32; d <<= 1) {
        sum += __shfl_xor_sync(0xffffffffu, sum, d);
        ss  += __shfl_xor_sync(0xffffffffu, ss, d);
    }
    if ((tid & 31) == 0) {
        atomicAdd(&dg_sum[0][o], (double)sum);
        atomicAdd(&dg_ssq[0][o], (double)ss);
    }
}

__global__ void k_finalize(int stage, int C, float cnt,
                           const float* __restrict__ g, const float* __restrict__ be,
                           float* __restrict__ sc, float* __restrict__ sh) {
    int c = threadIdx.x;
    if (c < C) {
        double mu  = dg_sum[stage][c] / (double)cnt;
        double var = dg_ssq[stage][c] / (double)cnt - mu*mu;
        float scale = g[c] * (float)(1.0 / sqrt(var + 1e-5));
        sc[c] = scale;
        sh[c] = be[c] - (float)mu * scale;
    }
}

// ====== edge-domain SGEMM: FFMA2, cp.async double-buffered (in-place xform),
//        fused stats + max. Static smem only. (conv2/conv3) ======
template<int MI, bool WRITE>
__global__ void __launch_bounds__(256, 2) k_egemm(
        const float* __restrict__ A, const float* __restrict__ Wt,
        const float* __restrict__ bias,
        const float* __restrict__ sc, const float* __restrict__ sh,
        float* __restrict__ Out, int M, int K, int stage, int zoff) {
    __shared__ float As[2][16*160];
    __shared__ float Ws[2][16*MI*16];
    const int WT = MI*16;
    unsigned Asu = smem_u32(As);
    unsigned Wsu = smem_u32(Ws);
    int b = blockIdx.z;
    const float* Ab = A + (size_t)b*K*NT;
    int m0 = blockIdx.y*WT, t0 = blockIdx.x*160;
    int tid = threadIdx.x, tx = tid & 15, ty = tid >> 4;
    int KT = K >> 4;

    ull acc[MI][5];
    #pragma unroll
    for (int i = 0; i < MI; i++)
        #pragma unroll
        for (int q = 0; q < 5; q++) acc[i][q] = 0ull;

#define EG_LOAD(KT_IDX, BI) do { \
        int k0_ = (KT_IDX) << 4; \
        _Pragma("unroll") \
        for (int i_ = 0; i_ < 3; i_++) { int e_ = tid + i_*256; if (e_ < 640) { \
            int r_ = e_/40, c_ = (e_%40)*4; \
            CPA16(Asu + (unsigned)((BI)*2560 + r_*160 + c_)*4u, \
                  Ab + (size_t)(k0_+r_)*NT + t0 + c_); } } \
        _Pragma("unroll") \
        for (int i_ = 0; i_ < (MI > 4 ? 2 : 1); i_++) { int e_ = tid + i_*256; if (e_ < MI*64) { \
            int r_ = e_/(MI*4), c_ = (e_%(MI*4))*4; \
            CPA16(Wsu + (unsigned)((BI)*16*WT + r_*WT + c_)*4u, \
                  Wt + (size_t)(k0_+r_)*M + m0 + c_); } } \
        CPA_COMMIT(); \
    } while (0)

#define EG_XFORM(BI, K0) do { \
        _Pragma("unroll") \
        for (int i_ = 0; i_ < 3; i_++) { int e_ = tid + i_*256; if (e_ < 640) { \
            int r_ = e_/40, c_ = (e_%40)*4; \
            float4 v_ = *(float4*)&As[BI][r_*160 + c_]; \
            float s_ = sc[(K0)+r_], h_ = sh[(K0)+r_]; \
            LRELU4(v_, s_, h_); \
            *(float4*)&As[BI][r_*160 + c_] = v_; } } \
    } while (0)

    EG_LOAD(0, 0);
    EG_LOAD(1, 1);
    CPA_WAIT1();
    __syncthreads();
    EG_XFORM(0, 0);
    __syncthreads();

    for (int kt = 0; kt < KT; kt++) {
        int cb = kt & 1, nb = cb ^ 1;
        const float* An = As[cb];
        const float* Wn = Ws[cb];
        #pragma unroll
        for (int kk = 0; kk < 16; kk++) {
            const ull* arow = (const ull*)&An[kk*160 + tx*10];
            ull ap[5];
            #pragma unroll
            for (int q = 0; q < 5; q++) ap[q] = arow[q];
            float wv[MI];
            #pragma unroll
            for (int h = 0; h < MI; h += 4) {
                float4 wf = *(const float4*)&Wn[kk*WT + ty*MI + h];
                wv[h] = wf.x; wv[h+1] = wf.y; wv[h+2] = wf.z; wv[h+3] = wf.w;
            }
            #pragma unroll
            for (int i = 0; i < MI; i++) {
                ull wp; DUP2(wp, wv[i]);
                #pragma unroll
                for (int q = 0; q < 5; q++) FMA2(acc[i][q], ap[q], wp);
            }
        }
        if (kt + 1 < KT) {
            CPA_WAIT0();
            __syncthreads();
            EG_XFORM(nb, (kt+1) << 4);
            if (kt + 2 < KT) EG_LOAD(kt+2, cb);
            __syncthreads();
        }
    }
#undef EG_LOAD
#undef EG_XFORM

    float* Ob = WRITE ? (Out + (size_t)b*M*NT) : (float*)0;
    #pragma unroll
    for (int i = 0; i < MI; i++) {
        int m = m0 + ty*MI + i;
        float bv = bias[m];
        float sum = 0.f, ss = 0.f, mxv = -INFINITY;
        #pragma unroll
        for (int q = 0; q < 5; q++) {
            float lo, hi;
            UNPK2(lo, hi, acc[i][q]);
            lo += bv; hi += bv;
            if (WRITE)
                *(float2*)(Ob + (size_t)m*NT + t0 + tx*10 + 2*q) = make_float2(lo, hi);
            sum += lo + hi;
            ss = fmaf(lo, lo, ss); ss = fmaf(hi, hi, ss);
            mxv = fmaxf(mxv, fmaxf(lo, hi));
        }
        #pragma unroll
        for (int d = 1; d < 16; d <<= 1) {
            sum += __shfl_xor_sync(0xffffffffu, sum, d);
            ss  += __shfl_xor_sync(0xffffffffu, ss, d);
        }
        if (tx == 0) {
            atomicAdd(&dg_sum[stage][m], (double)sum);
            atomicAdd(&dg_ssq[stage][m], (double)ss);
        }
        float mo = fmaxf(mxv, __shfl_xor_sync(0xffffffffu, mxv, 1));
        if ((tx & 1) == 0)
            dg_z[((size_t)b*512 + zoff + m)*NP + blockIdx.x*8 + (tx >> 1)] = mo;
    }
}

// ====== conv4 via legacy tensor-core mma.sync (bf16-split), stats+max only ===
// Block: 256 thr (8 warps), tile M=128 x T=80, K=128 in 8 k16 steps.
// smem byte layout (static 47616):
//   raw fp32 [2][16][80]      @ 0      (5120 each)
//   Bh bf16  [2][80][20]      @ 10240  (3200 each)  rows padded to 40B
//   Bl bf16  [2][80][20]      @ 16640
//   Wh bf16  [2][128][24]     @ 23040  (6144 each)  rows padded to 48B
//   Wl bf16  [2][128][24]     @ 35328
//   stage D fp32 [128][80]    @ 0      (reused after pipeline, 40960)
__global__ void __launch_bounds__(256, 2) k_m4(
        const float* __restrict__ A,
        const __nv_bfloat16* __restrict__ W4h, const __nv_bfloat16* __restrict__ W4l,
        const float* __restrict__ bias,
        const float* __restrict__ sc, const float* __restrict__ sh,
        int stage, int zoff) {
    __shared__ alignas(16) char S[47616];
    unsigned Su = smem_u32(S);
    int tid = threadIdx.x, w = tid >> 5, lane = tid & 31;
    int b = blockIdx.z, t0 = blockIdx.x*80, m0 = blockIdx.y*128;
    const float* Ab = A + (size_t)b*128*NT;

    const unsigned RAW = 0, BH = 10240, BL = 16640, WH = 23040, WL = 35328;

#define M4_LOAD(KT_IDX, BI) do { \
        int k0_ = (KT_IDX) << 4; \
        _Pragma("unroll") \
        for (int i_ = 0; i_ < 2; i_++) { int e_ = tid + i_*256; if (e_ < 320) { \
            int r_ = e_/20, c_ = (e_%20)*4; \
            CPA16(Su + RAW + (BI)*5120u + (unsigned)e_*16u, \
                  Ab + (size_t)(k0_+r_)*NT + t0 + c_); } } \
        { int r_ = tid >> 1, hf_ = tid & 1; \
          size_t go_ = ((size_t)(m0+r_)*128 + k0_ + hf_*8)*2; \
          CPA16(Su + WH + (BI)*6144u + (unsigned)(r_*48 + hf_*16), (const char*)W4h + go_); \
          CPA16(Su + WL + (BI)*6144u + (unsigned)(r_*48 + hf_*16), (const char*)W4l + go_); } \
        CPA_COMMIT(); \
    } while (0)

#define M4_XFORM(BI, K0) do { \
        _Pragma("unroll") \
        for (int i_ = 0; i_ < 5; i_++) { int e_ = tid*5 + i_; \
            int k_ = e_/80, t_ = e_%80; \
            float v_ = *(const float*)(S + RAW + (BI)*5120 + e_*4); \
            v_ = fmaf(v_, sc[(K0)+k_], sh[(K0)+k_]); \
            v_ = v_ >= 0.f ? v_ : SLOPE*v_; \
            __nv_bfloat16 hb_ = __float2bfloat16(v_); \
            __nv_bfloat16 lb_ = __float2bfloat16(v_ - __bfloat162float(hb_)); \
            *(__nv_bfloat16*)(S + BH + (BI)*3200 + t_*40 + k_*2) = hb_; \
            *(__nv_bfloat16*)(S + BL + (BI)*3200 + t_*40 + k_*2) = lb_; } \
    } while (0)

    float c[10][4];
    #pragma unroll
    for (int j = 0; j < 10; j++)
        #pragma unroll
        for (int q = 0; q < 4; q++) c[j][q] = 0.f;

    int g = lane >> 2, q4 = (lane & 3) * 4;

    M4_LOAD(0, 0);
    M4_LOAD(1, 1);
    CPA_WAIT1();
    __syncthreads();
    M4_XFORM(0, 0);
    __syncthreads();

    for (int kt = 0; kt < 8; kt++) {
        int cb = kt & 1, nb = cb ^ 1;
        const char* Wp = S + WH + cb*6144;
        const char* Wq = S + WL + cb*6144;
        const char* Bp = S + BH + cb*3200;
        const char* Bq = S + BL + cb*3200;
        // A fragments for this warp's m-tile (rows w*16 .. w*16+15)
        unsigned ah0 = *(const unsigned*)(Wp + (w*16+g)*48 + q4);
        unsigned ah1 = *(const unsigned*)(Wp + (w*16+g+8)*48 + q4);
        unsigned ah2 = *(const unsigned*)(Wp + (w*16+g)*48 + 16 + q4);
        unsigned ah3 = *(const unsigned*)(Wp + (w*16+g+8)*48 + 16 + q4);
        unsigned al0 = *(const unsigned*)(Wq + (w*16+g)*48 + q4);
        unsigned al1 = *(const unsigned*)(Wq + (w*16+g+8)*48 + q4);
        unsigned al2 = *(const unsigned*)(Wq + (w*16+g)*48 + 16 + q4);
        unsigned al3 = *(const unsigned*)(Wq + (w*16+g+8)*48 + 16 + q4);
        #pragma unroll
        for (int j = 0; j < 10; j++) {
            int n = j*8 + g;
            unsigned bh0 = *(const unsigned*)(Bp + n*40 + q4);
            unsigned bh1 = *(const unsigned*)(Bp + n*40 + 16 + q4);
            unsigned bl0 = *(const unsigned*)(Bq + n*40 + q4);
            unsigned bl1 = *(const unsigned*)(Bq + n*40 + 16 + q4);
            MMA_BF16(c[j], ah0, ah1, ah2, ah3, bh0, bh1);
            MMA_BF16(c[j], ah0, ah1, ah2, ah3, bl0, bl1);
            MMA_BF16(c[j], al0, al1, al2, al3, bh0, bh1);
        }
        if (kt + 1 < 8) {
            CPA_WAIT0();
            __syncthreads();
            M4_XFORM(nb, (kt+1) << 4);
            if (kt + 2 < 8) M4_LOAD(kt+2, cb);
            __syncthreads();
        }
    }
#undef M4_LOAD
#undef M4_XFORM

    // stage accumulators to smem [128][80] fp32 (reuses pipeline space)
    __syncthreads();
    #pragma unroll
    for (int j = 0; j < 10; j++) {
        int col = j*8 + (lane & 3)*2;
        int r0 = w*16 + g;
        *(float2*)(S + (r0*80 + col)*4)     = make_float2(c[j][0], c[j][1]);
        *(float2*)(S + ((r0+8)*80 + col)*4) = make_float2(c[j][2], c[j][3]);
    }
    __syncthreads();

    // stats + max epilogue (R4 pattern): tx 0..7 cover 80 cols, ty 0..31 x4 rows
    int tx = tid & 7, ty = tid >> 3;
    #pragma unroll
    for (int i = 0; i < 4; i++) {
        int r = ty*4 + i;
        int m = m0 + r;
        float bv = bias[m];
        float sum = 0.f, ss = 0.f, mxv = -INFINITY;
        #pragma unroll
        for (int q = 0; q < 10; q++) {
            float v = *(const float*)(S + (r*80 + tx*10 + q)*4) + bv;
            sum += v;
            ss = fmaf(v, v, ss);
            mxv = fmaxf(mxv, v);
        }
        #pragma unroll
        for (int d = 1; d < 8; d <<= 1) {
            sum += __shfl_xor_sync(0xffffffffu, sum, d);
            ss  += __shfl_xor_sync(0xffffffffu, ss, d);
        }
        if (tx == 0) {
            atomicAdd(&dg_sum[stage][m], (double)sum);
            atomicAdd(&dg_ssq[stage][m], (double)ss);
        }
        float mo = fmaxf(mxv, __shfl_xor_sync(0xffffffffu, mxv, 1));
        if ((tx & 1) == 0)
            dg_z[((size_t)b*512 + zoff + m)*NP + blockIdx.x*4 + (tx >> 1)] = mo;
    }
}

// ====== point-domain SGEMM: FFMA2, cp.async double-buffered (in-place xform),
//        fused stats. Static smem only. ======
template<int MI>
__global__ void __launch_bounds__(256, 2) k_pgemm(
        const float* __restrict__ A, const float* __restrict__ Wt,
        const float* __restrict__ bias,
        const float* __restrict__ sc, const float* __restrict__ sh,
        float* __restrict__ Out, int M, int K, int stage) {
    __shared__ float As[2][16*128];
    __shared__ float Ws[2][16*MI*16];
    const int WT = MI*16;
    unsigned Asu = smem_u32(As);
    unsigned Wsu = smem_u32(Ws);
    int b = blockIdx.z;
    const float* Ab = A + (size_t)b*K*NP;
    float* Ob = Out + (size_t)b*M*NP;
    int m0 = blockIdx.y*WT, t0 = blockIdx.x*128;
    int tid = threadIdx.x, tx = tid & 15, ty = tid >> 4;
    int KT = K >> 4;

    ull acc[MI][4];
    #pragma unroll
    for (int i = 0; i < MI; i++)
        #pragma unroll
        for (int q = 0; q < 4; q++) acc[i][q] = 0ull;

#define PG_LOAD(KT_IDX, BI) do { \
        int k0_ = (KT_IDX) << 4; \
        _Pragma("unroll") \
        for (int i_ = 0; i_ < 2; i_++) { int e_ = tid + i_*256; \
            int r_ = e_ >> 5, c_ = (e_ & 31)*4; \
            CPA16(Asu + (unsigned)((BI)*2048 + r_*128 + c_)*4u, \
                  Ab + (size_t)(k0_+r_)*NP + t0 + c_); } \
        _Pragma("unroll") \
        for (int i_ = 0; i_ < (MI > 4 ? 2 : 1); i_++) { int e_ = tid + i_*256; if (e_ < MI*64) { \
            int r_ = e_/(MI*4), c_ = (e_%(MI*4))*4; \
            CPA16(Wsu + (unsigned)((BI)*16*WT + r_*WT + c_)*4u, \
                  Wt + (size_t)(k0_+r_)*M + m0 + c_); } } \
        CPA_COMMIT(); \
    } while (0)

#define PG_XFORM(BI, K0) do { \
        _Pragma("unroll") \
        for (int i_ = 0; i_ < 2; i_++) { int e_ = tid + i_*256; \
            int r_ = e_ >> 5, c_ = (e_ & 31)*4; \
            float4 v_ = *(float4*)&As[BI][r_*128 + c_]; \
            float s_ = sc[(K0)+r_], h_ = sh[(K0)+r_]; \
            LRELU4(v_, s_, h_); \
            *(float4*)&As[BI][r_*128 + c_] = v_; } \
    } while (0)

    PG_LOAD(0, 0);
    PG_LOAD(1, 1);
    CPA_WAIT1();
    __syncthreads();
    PG_XFORM(0, 0);
    __syncthreads();

    for (int kt = 0; kt < KT; kt++) {
        int cb = kt & 1, nb = cb ^ 1;
        const float* An = As[cb];
        const float* Wn = Ws[cb];
        #pragma unroll
        for (int kk = 0; kk < 16; kk++) {
            const ull* arow = (const ull*)&An[kk*128];
            ull ap[4];
            #pragma unroll
            for (int q = 0; q < 4; q++) ap[q] = arow[tx + 16*q];
            float wv[MI];
            #pragma unroll
            for (int h = 0; h < MI; h += 4) {
                float4 wf = *(const float4*)&Wn[kk*WT + ty*MI + h];
                wv[h] = wf.x; wv[h+1] = wf.y; wv[h+2] = wf.z; wv[h+3] = wf.w;
            }
            #pragma unroll
            for (int i = 0; i < MI; i++) {
                ull wp; DUP2(wp, wv[i]);
                #pragma unroll
                for (int q = 0; q < 4; q++) FMA2(acc[i][q], ap[q], wp);
            }
        }
        if (kt + 1 < KT) {
            CPA_WAIT0();
            __syncthreads();
            PG_XFORM(nb, (kt+1) << 4);
            if (kt + 2 < KT) PG_LOAD(kt+2, cb);
            __syncthreads();
        }
    }
#undef PG_LOAD
#undef PG_XFORM

    #pragma unroll
    for (int i = 0; i < MI; i++) {
        int m = m0 + ty*MI + i;
        float bv = bias[m];
        float sum = 0.f, ss = 0.f;
        #pragma unroll
        for (int q = 0; q < 4; q++) {
            float lo, hi;
            UNPK2(lo, hi, acc[i][q]);
            lo += bv; hi += bv;
            *(float2*)(Ob + (size_t)m*NP + t0 + 2*tx + 32*q) = make_float2(lo, hi);
            sum += lo + hi;
            ss = fmaf(lo, lo, ss); ss = fmaf(hi, hi, ss);
        }
        #pragma unroll
        for (int d = 1; d < 16; d <<= 1) {
            sum += __shfl_xor_sync(0xffffffffu, sum, d);
            ss  += __shfl_xor_sync(0xffffffffu, ss, d);
        }
        if (tx == 0) {
            atomicAdd(&dg_sum[stage][m], (double)sum);
            atomicAdd(&dg_ssq[stage][m], (double)ss);
        }
    }
}

// final bn+lrelu + (B,C,N) -> (B,N,C) transpose
__global__ void k_out(float* __restrict__ out) {
    __shared__ float st[32][33];
    int b = blockIdx.z;
    int c0 = blockIdx.y*32, n0 = blockIdx.x*32;
    int tx = threadIdx.x, ty = threadIdx.y;
    int c = c0 + ty;
    float v = dg_o6[((size_t)b*1024 + c)*NP + n0 + tx];
    v = fmaf(v, dg_sc6[c], dg_sh6[c]);
    st[ty][tx] = v >= 0.f ? v : SLOPE*v;
    __syncthreads();
    out[((size_t)b*NP + n0 + ty)*1024 + c0 + tx] = st[tx][ty];
}

// ---------------- host orchestration ----------------

extern "C" void kernel_launch(void* const* d_in, const int* in_sizes, int n_in,
                              void* d_out, int out_size) {
    (void)in_sizes; (void)n_in; (void)out_size;
    const float* x  = (const float*)d_in[0];
    const float* w1 = (const float*)d_in[1];
    const float* b1 = (const float*)d_in[2];
    const float* g1 = (const float*)d_in[3];
    const float* be1= (const float*)d_in[4];
    const float* w2 = (const float*)d_in[5];
    const float* b2 = (const float*)d_in[6];
    const float* g2 = (const float*)d_in[7];
    const float* be2= (const float*)d_in[8];
    const float* w3 = (const float*)d_in[9];
    const float* b3 = (const float*)d_in[10];
    const float* g3 = (const float*)d_in[11];
    const float* be3= (const float*)d_in[12];
    const float* w4 = (const float*)d_in[13];
    const float* b4 = (const float*)d_in[14];
    const float* g4 = (const float*)d_in[15];
    const float* be4= (const float*)d_in[16];
    const float* w5 = (const float*)d_in[17];
    const float* b5 = (const float*)d_in[18];
    const float* g5 = (const float*)d_in[19];
    const float* be5= (const float*)d_in[20];
    const float* w6 = (const float*)d_in[21];
    const float* b6 = (const float*)d_in[22];
    const float* g6 = (const float*)d_in[23];
    const float* be6= (const float*)d_in[24];

    float *p_h1, *p_h2, *p_h3, *p_z, *p_o5, *p_o6;
    float *p_scZ, *p_shZ, *p_sc5, *p_sh5, *p_sc6, *p_sh6;
    float *p_w2t, *p_w3t, *p_w5t, *p_w6t;
    __nv_bfloat16 *p_w4h, *p_w4l;
    cudaGetSymbolAddress((void**)&p_h1, dg_h1);
    cudaGetSymbolAddress((void**)&p_h2, dg_h2);
    cudaGetSymbolAddress((void**)&p_h3, dg_h3);
    cudaGetSymbolAddress((void**)&p_z,  dg_z);
    cudaGetSymbolAddress((void**)&p_o5, dg_o5);
    cudaGetSymbolAddress((void**)&p_o6, dg_o6);
    cudaGetSymbolAddress((void**)&p_scZ, dg_scZ);
    cudaGetSymbolAddress((void**)&p_shZ, dg_shZ);
    cudaGetSymbolAddress((void**)&p_sc5, dg_sc5);
    cudaGetSymbolAddress((void**)&p_sh5, dg_sh5);
    cudaGetSymbolAddress((void**)&p_sc6, dg_sc6);
    cudaGetSymbolAddress((void**)&p_sh6, dg_sh6);
    cudaGetSymbolAddress((void**)&p_w2t, dg_w2t);
    cudaGetSymbolAddress((void**)&p_w3t, dg_w3t);
    cudaGetSymbolAddress((void**)&p_w5t, dg_w5t);
    cudaGetSymbolAddress((void**)&p_w6t, dg_w6t);
    cudaGetSymbolAddress((void**)&p_w4h, dg_w4h);
    cudaGetSymbolAddress((void**)&p_w4l, dg_w4l);

    const float cntE = (float)(NB*NP*NK);
    const float cntP = (float)(NB*NP);

    k_zero<<<6, 1024>>>();
    k_wt<<<dim3(64/32, 64/32), dim3(32, 32)>>>(w2, p_w2t, 64, 64);
    k_wt<<<dim3(64/32, 128/32), dim3(32, 32)>>>(w3, p_w3t, 128, 64);
    k_wt<<<dim3(512/32, 256/32), dim3(32, 32)>>>(w5, p_w5t, 256, 512);
    k_wt<<<dim3(256/32, 1024/32), dim3(32, 32)>>>(w6, p_w6t, 1024, 256);
    k_wsplit<<<(256*128 + 255)/256, 256>>>(w4, p_w4h, p_w4l, 256*128);
    k_xx<<<NB, NP>>>(x);
    k_pdist<<<dim3(NP/32, NP/32, NB), dim3(8, 16)>>>(x);
    k_topk<<<NB*NP/8, 256>>>();
    k_ps<<<dim3(NP/256, 64, NB), 256>>>(x, w1);

    k_h1<<<dim3(NP/256, 64, NB), 256>>>(b1);
    k_finalize<<<1, 64>>>(0, 64, cntE, g1, be1, p_scZ, p_shZ);

    // conv2: 64 <- 64 (MI=4)
    k_egemm<4, true><<<dim3(NT/160, 1, NB), 256>>>(p_h1, p_w2t, b2, p_scZ, p_shZ, p_h2, 64, 64, 1, 64);
    k_finalize<<<1, 64>>>(1, 64, cntE, g2, be2, p_scZ + 64, p_shZ + 64);

    // conv3: 128 <- 64 (MI=8)
    k_egemm<8, true><<<dim3(NT/160, 1, NB), 256>>>(p_h2, p_w3t, b3, p_scZ + 64, p_shZ + 64, p_h3, 128, 64, 2, 128);
    k_finalize<<<1, 128>>>(2, 128, cntE, g3, be3, p_scZ + 128, p_shZ + 128);

    // conv4: 256 <- 128, tensor-core mma (bf16-split), stats+max only
    k_m4<<<dim3(NT/80, 2, NB), 256>>>(p_h3, p_w4h, p_w4l, b4, p_scZ + 128, p_shZ + 128, 3, 256);
    k_finalize<<<1, 256>>>(3, 256, cntE, g4, be4, p_scZ + 256, p_shZ + 256);

    // conv5: 256 <- 512 over points
    k_pgemm<8><<<dim3(NP/128, 2, NB), 256>>>(p_z, p_w5t, b5, p_scZ, p_shZ, p_o5, 256, 512, 4);
    k_finalize<<<1, 256>>>(4, 256, cntP, g5, be5, p_sc5, p_sh5);

    // conv6: 1024 <- 256
    k_pgemm<8><<<dim3(NP/128, 8, NB), 256>>>(p_o5, p_w6t, b6, p_sc5, p_sh5, p_o6, 1024, 256, 5);
    k_finalize<<<1, 1024>>>(5, 1024, cntP, g6, be6, p_sc6, p_sh6);

    k_out<<<dim3(NP/32, 1024/32, NB), dim3(32, 32)>>>((float*)d_out);
}

// round 12
// speedup vs baseline: 1.0015x; 1.0015x over previous
#include <cuda_runtime.h>
#include <math.h>

#define NB 8
#define ND 60
#define NP 1024
#define NK 20
#define NT (NP*NK)
#define SLOPE 0.2f

typedef unsigned long long ull;

// ---------------- device scratch ----------------
static __device__ float dg_pd[NB*NP*NP];
static __device__ float dg_xx[NB*NP];
static __device__ int   dg_idx[NB*NP*NK];
static __device__ float dg_P[NB*64*NP];
static __device__ float dg_S[NB*64*NP];
static __device__ float dg_h2[NB*64*NT];
static __device__ float dg_h3[NB*128*NT];
static __device__ float dg_z [NB*512*NP];
static __device__ float dg_o5[NB*256*NP];
static __device__ float dg_o6[NB*1024*NP];
static __device__ double dg_sum[6][1024];
static __device__ double dg_ssq[6][1024];
static __device__ float dg_scZ[512], dg_shZ[512];
static __device__ float dg_sc5[256], dg_sh5[256];
static __device__ float dg_sc6[1024], dg_sh6[1024];
// pre-transposed weights Wt[k][m]
static __device__ float dg_w2t[64*64];
static __device__ float dg_w3t[64*128];
static __device__ float dg_w4t[128*256];
static __device__ float dg_w5t[512*256];
static __device__ float dg_w6t[256*1024];

// packed fp32x2 FMA (sm_103a) — exact fp32 numerics per lane, 2x rate
#define FMA2(d, a, bb) asm("fma.rn.f32x2 %0, %1, %2, %0;" : "+l"(d) : "l"(a), "l"(bb))
#define DUP2(d, f)     asm("mov.b64 %0, {%1, %1};" : "=l"(d) : "f"(f))
#define UNPK2(lo, hi, d) asm("mov.b64 {%0, %1}, %2;" : "=f"(lo), "=f"(hi) : "l"(d))

#define LRELU4(v, s, h)                                           \
    v.x = fmaf(v.x, s, h); v.x = v.x >= 0.f ? v.x : SLOPE*v.x;    \
    v.y = fmaf(v.y, s, h); v.y = v.y >= 0.f ? v.y : SLOPE*v.y;    \
    v.z = fmaf(v.z, s, h); v.z = v.z >= 0.f ? v.z : SLOPE*v.z;    \
    v.w = fmaf(v.w, s, h); v.w = v.w >= 0.f ? v.w : SLOPE*v.w;

// cp.async helpers (sm_80+ baseline PTX — valid on plain compute_103)
#define CPA16(dst_u32, gptr) \
    asm volatile("cp.async.ca.shared.global [%0], [%1], 16;" :: "r"(dst_u32), "l"(gptr) : "memory")
#define CPA_COMMIT() asm volatile("cp.async.commit_group;" ::: "memory")
#define CPA_WAIT0()  asm volatile("cp.async.wait_group 0;" ::: "memory")
#define CPA_WAIT1()  asm volatile("cp.async.wait_group 1;" ::: "memory")

static __device__ __forceinline__ unsigned smem_u32(const void* p) {
    unsigned a;
    asm("{ .reg .u64 t; cvta.to.shared.u64 t, %1; cvt.u32.u64 %0, t; }" : "=r"(a) : "l"(p));
    return a;
}

// ---------------- small kernels ----------------

__global__ void k_zero() {
    int i = blockIdx.x*1024 + threadIdx.x;
    ((double*)dg_sum)[i] = 0.0;
    ((double*)dg_ssq)[i] = 0.0;
}

// w[m][k] -> wt[k][m]; dims multiples of 32
__global__ void k_wt(const float* __restrict__ w, float* __restrict__ wt, int M, int K) {
    __shared__ float t[32][33];
    int k0 = blockIdx.x*32, m0 = blockIdx.y*32;
    int tx = threadIdx.x, ty = threadIdx.y;
    t[ty][tx] = w[(size_t)(m0+ty)*K + k0 + tx];
    __syncthreads();
    wt[(size_t)(k0+ty)*M + m0 + tx] = t[tx][ty];
}

__global__ void k_xx(const float* __restrict__ x) {
    int b = blockIdx.x, n = threadIdx.x;
    float s = 0.f;
    #pragma unroll
    for (int d = 0; d < ND; d++) {
        float v = x[((size_t)b*ND + d)*NP + n];
        s = fmaf(v, v, s);
    }
    dg_xx[b*NP + n] = s;
}

// pd[b,n,m] = 2*dot(x_n,x_m) - xx_n - xx_m
__global__ void __launch_bounds__(128) k_pdist(const float* __restrict__ x) {
    __shared__ float sn[ND][32], sm[ND][32];
    int b = blockIdx.z;
    int n0 = blockIdx.y*32, m0 = blockIdx.x*32;
    int tx = threadIdx.x, ty = threadIdx.y;
    int tid = ty*8 + tx;
    for (int e = tid; e < ND*32; e += 128) {
        int d = e >> 5, c = e & 31;
        size_t base = ((size_t)b*ND + d)*NP;
        sn[d][c] = x[base + n0 + c];
        sm[d][c] = x[base + m0 + c];
    }
    __syncthreads();
    ull acc[2][2] = {{0ull,0ull},{0ull,0ull}};
    #pragma unroll
    for (int d = 0; d < ND; d++) {
        ull sn2 = *(const ull*)&sn[d][ty*2];
        float nlo, nhi; UNPK2(nlo, nhi, sn2);
        ull dlo, dhi; DUP2(dlo, nlo); DUP2(dhi, nhi);
        ull mp0 = *(const ull*)&sm[d][tx*4];
        ull mp1 = *(const ull*)&sm[d][tx*4+2];
        FMA2(acc[0][0], mp0, dlo); FMA2(acc[0][1], mp1, dlo);
        FMA2(acc[1][0], mp0, dhi); FMA2(acc[1][1], mp1, dhi);
    }
    float xm[4];
    #pragma unroll
    for (int j = 0; j < 4; j++) xm[j] = dg_xx[b*NP + m0 + tx*4 + j];
    #pragma unroll
    for (int i = 0; i < 2; i++) {
        int n = n0 + ty*2 + i;
        float xn = dg_xx[b*NP + n];
        float v0, v1, v2, v3;
        UNPK2(v0, v1, acc[i][0]);
        UNPK2(v2, v3, acc[i][1]);
        float4 o = make_float4(2.f*v0 - xn - xm[0], 2.f*v1 - xn - xm[1],
                               2.f*v2 - xn - xm[2], 2.f*v3 - xn - xm[3]);
        *(float4*)(dg_pd + ((size_t)b*NP + n)*NP + m0 + tx*4) = o;
    }
}

// warp-per-row top-20 via per-lane bitonic sort of packed (value,idx) keys
__global__ void k_topk() {
    int warp = threadIdx.x >> 5, lane = threadIdx.x & 31;
    int row = blockIdx.x*8 + warp;
    const float* rp = dg_pd + (size_t)row*NP;
    ull k[32];
    #pragma unroll
    for (int i = 0; i < 8; i++) {
        float4 t = *(const float4*)(rp + i*128 + lane*4);
        float vv[4] = {t.x, t.y, t.z, t.w};
        #pragma unroll
        for (int j = 0; j < 4; j++) {
            unsigned fb = __float_as_uint(vv[j]);
            unsigned u = (fb & 0x80000000u) ? ~fb : (fb | 0x80000000u);
            unsigned idx = (unsigned)(i*128 + lane*4 + j);
            k[i*4+j] = ((ull)u << 32) | (ull)(0xFFFFFFFFu - idx);
        }
    }
    #pragma unroll
    for (int sz = 2; sz <= 32; sz <<= 1) {
        #pragma unroll
        for (int st = sz >> 1; st > 0; st >>= 1) {
            #pragma unroll
            for (int i = 0; i < 32; i++) {
                int j = i ^ st;
                if (j > i) {
                    bool sw = ((i & sz) == 0) ? (k[i] < k[j]) : (k[i] > k[j]);
                    if (sw) { ull t = k[i]; k[i] = k[j]; k[j] = t; }
                }
            }
        }
    }
    int* outp = dg_idx + (size_t)row*NK;
    #pragma unroll
    for (int t = 0; t < NK; t++) {
        ull best = k[0];
        #pragma unroll
        for (int d = 16; d; d >>= 1) {
            ull o = __shfl_xor_sync(0xffffffffu, best, d);
            if (o > best) best = o;
        }
        if (lane == 0) outp[t] = (int)(0xFFFFFFFFu - (unsigned)(best & 0xFFFFFFFFull));
        if (k[0] == best) {
            #pragma unroll
            for (int j = 0; j < 20; j++) k[j] = k[j+1];
        }
    }
}

__global__ void k_ps(const float* __restrict__ x, const float* __restrict__ w1) {
    __shared__ float wa[ND], ws[ND];
    int o = blockIdx.y, b = blockIdx.z, tid = threadIdx.x;
    if (tid < ND) {
        float a = w1[o*120 + tid];
        wa[tid] = a;
        ws[tid] = w1[o*120 + 60 + tid] - a;
    }
    __syncthreads();
    int n = blockIdx.x*256 + tid;
    float p = 0.f, s = 0.f;
    #pragma unroll
    for (int d = 0; d < ND; d++) {
        float xv = x[((size_t)b*ND + d)*NP + n];
        p = fmaf(wa[d], xv, p);
        s = fmaf(ws[d], xv, s);
    }
    dg_P[((size_t)b*64 + o)*NP + n] = p;
    dg_S[((size_t)b*64 + o)*NP + n] = s;
}

// conv1 stats(stage0) + max -> z[0:64)  WITHOUT materializing h1
__global__ void k_h1ns(const float* __restrict__ b1) {
    int tid = threadIdx.x;
    int n = blockIdx.x*256 + tid;
    int o = blockIdx.y, b = blockIdx.z;
    float sv = dg_S[((size_t)b*64 + o)*NP + n] + b1[o];
    const float* Pb = dg_P + ((size_t)b*64 + o)*NP;
    const int* ip = dg_idx + ((size_t)b*NP + n)*NK;
    float sum = 0.f, ss = 0.f, mx = -INFINITY;
    #pragma unroll
    for (int j = 0; j < NK; j++) {
        float v = Pb[ip[j]] + sv;
        sum += v;
        ss = fmaf(v, v, ss);
        mx = fmaxf(mx, v);
    }
    dg_z[((size_t)b*512 + o)*NP + n] = mx;
    #pragma unroll
    for (int d = 1; d < 32; d <<= 1) {
        sum += __shfl_xor_sync(0xffffffffu, sum, d);
        ss  += __shfl_xor_sync(0xffffffffu, ss, d);
    }
    if ((tid & 31) == 0) {
        atomicAdd(&dg_sum[0][o], (double)sum);
        atomicAdd(&dg_ssq[0][o], (double)ss);
    }
}

__global__ void k_finalize(int stage, int C, float cnt,
                           const float* __restrict__ g, const float* __restrict__ be,
                           float* __restrict__ sc, float* __restrict__ sh) {
    int c = threadIdx.x;
    if (c < C) {
        double mu  = dg_sum[stage][c] / (double)cnt;
        double var = dg_ssq[stage][c] / (double)cnt - mu*mu;
        float scale = g[c] * (float)(1.0 / sqrt(var + 1e-5));
        sc[c] = scale;
        sh[c] = be[c] - (float)mu * scale;
    }
}

// ====== conv2 GEMM with on-the-fly gathered A (h1 never materialized) ======
// A[o][t] = lrelu((P[o, idx[pt,j]] + S[o,pt] + b1[o])*sc[o] + sh[o]); M=64, K=64.
__global__ void __launch_bounds__(256, 2) k_g2(
        const float* __restrict__ Wt,    // w2t [k][m] 64x64
        const float* __restrict__ b1,
        const float* __restrict__ bias,  // b2
        const float* __restrict__ sc, const float* __restrict__ sh,
        float* __restrict__ Out) {
    __shared__ float Ws[4][16*64];
    __shared__ float As[16*160];
    __shared__ int   sidx[160];
    __shared__ float stab[64][8];
    int b = blockIdx.z;
    int t0 = blockIdx.x*160, n0 = blockIdx.x*8;
    int tid = threadIdx.x, tx = tid & 15, ty = tid >> 4;

    // all of W (64x64) via cp.async: 1024 float4, 4/thread
    unsigned Wsu = smem_u32(Ws);
    #pragma unroll
    for (int i = 0; i < 4; i++) {
        int e = tid + i*256;
        CPA16(Wsu + (unsigned)e*16u, Wt + (size_t)(e >> 4)*64 + (e & 15)*4);
    }
    CPA_COMMIT();
    if (tid < 160)
        sidx[tid] = dg_idx[((size_t)b*NP + n0 + tid/20)*NK + tid%20];
    #pragma unroll
    for (int i = 0; i < 2; i++) {
        int e = tid + i*256;
        int r = e >> 3, p = e & 7;
        stab[r][p] = dg_S[((size_t)b*64 + r)*NP + n0 + p] + b1[r];
    }
    __syncthreads();   // sidx/stab visible before gathers

    const float* Pb = dg_P + (size_t)b*64*NP;
    float pa[10];
    int er[10], et[10];
    #pragma unroll
    for (int i = 0; i < 10; i++) {
        int e = tid + i*256;
        er[i] = e/160; et[i] = e%160;
        pa[i] = Pb[(size_t)er[i]*NP + sidx[et[i]]];
    }
    CPA_WAIT0();
    __syncthreads();   // W visible

    ull acc[4][5];
    #pragma unroll
    for (int i = 0; i < 4; i++)
        #pragma unroll
        for (int q = 0; q < 5; q++) acc[i][q] = 0ull;

    for (int kt = 0; kt < 4; kt++) {
        int k0 = kt << 4;
        #pragma unroll
        for (int i = 0; i < 10; i++) {
            int r = er[i], t = et[i];
            float v = pa[i] + stab[k0 + r][t/20];
            v = fmaf(v, sc[k0 + r], sh[k0 + r]);
            As[r*160 + t] = v >= 0.f ? v : SLOPE*v;
        }
        __syncthreads();
        if (kt + 1 < 4) {
            #pragma unroll
            for (int i = 0; i < 10; i++)
                pa[i] = Pb[(size_t)(k0 + 16 + er[i])*NP + sidx[et[i]]];
        }
        const float* Wn = Ws[kt];
        #pragma unroll
        for (int kk = 0; kk < 16; kk++) {
            const ull* arow = (const ull*)&As[kk*160 + tx*10];
            ull ap[5];
            #pragma unroll
            for (int q = 0; q < 5; q++) ap[q] = arow[q];
            float4 wf = *(const float4*)&Wn[kk*64 + ty*4];
            float wv[4] = {wf.x, wf.y, wf.z, wf.w};
            #pragma unroll
            for (int i = 0; i < 4; i++) {
                ull wp; DUP2(wp, wv[i]);
                #pragma unroll
                for (int q = 0; q < 5; q++) FMA2(acc[i][q], ap[q], wp);
            }
        }
        __syncthreads();
    }

    float* Ob = Out + (size_t)b*64*NT;
    #pragma unroll
    for (int i = 0; i < 4; i++) {
        int m = ty*4 + i;
        float bv = bias[m];
        float sum = 0.f, ss = 0.f, mxv = -INFINITY;
        #pragma unroll
        for (int q = 0; q < 5; q++) {
            float lo, hi;
            UNPK2(lo, hi, acc[i][q]);
            lo += bv; hi += bv;
            *(float2*)(Ob + (size_t)m*NT + t0 + tx*10 + 2*q) = make_float2(lo, hi);
            sum += lo + hi;
            ss = fmaf(lo, lo, ss); ss = fmaf(hi, hi, ss);
            mxv = fmaxf(mxv, fmaxf(lo, hi));
        }
        #pragma unroll
        for (int d = 1; d < 16; d <<= 1) {
            sum += __shfl_xor_sync(0xffffffffu, sum, d);
            ss  += __shfl_xor_sync(0xffffffffu, ss, d);
        }
        if (tx == 0) {
            atomicAdd(&dg_sum[1][m], (double)sum);
            atomicAdd(&dg_ssq[1][m], (double)ss);
        }
        float mo = fmaxf(mxv, __shfl_xor_sync(0xffffffffu, mxv, 1));
        if ((tx & 1) == 0)
            dg_z[((size_t)b*512 + 64 + m)*NP + blockIdx.x*8 + (tx >> 1)] = mo;
    }
}

// ====== edge-domain SGEMM: FFMA2, cp.async double-buffered (in-place xform),
//        fused stats + max. Static smem only. (conv3/conv4) ======
template<int MI, bool WRITE>
__global__ void __launch_bounds__(256, 2) k_egemm(
        const float* __restrict__ A, const float* __restrict__ Wt,
        const float* __restrict__ bias,
        const float* __restrict__ sc, const float* __restrict__ sh,
        float* __restrict__ Out, int M, int K, int stage, int zoff) {
    __shared__ float As[2][16*160];
    __shared__ float Ws[2][16*MI*16];
    const int WT = MI*16;
    unsigned Asu = smem_u32(As);
    unsigned Wsu = smem_u32(Ws);
    int b = blockIdx.z;
    const float* Ab = A + (size_t)b*K*NT;
    int m0 = blockIdx.y*WT, t0 = blockIdx.x*160;
    int tid = threadIdx.x, tx = tid & 15, ty = tid >> 4;
    int KT = K >> 4;

    ull acc[MI][5];
    #pragma unroll
    for (int i = 0; i < MI; i++)
        #pragma unroll
        for (int q = 0; q < 5; q++) acc[i][q] = 0ull;

#define EG_LOAD(KT_IDX, BI) do { \
        int k0_ = (KT_IDX) << 4; \
        _Pragma("unroll") \
        for (int i_ = 0; i_ < 3; i_++) { int e_ = tid + i_*256; if (e_ < 640) { \
            int r_ = e_/40, c_ = (e_%40)*4; \
            CPA16(Asu + (unsigned)((BI)*2560 + r_*160 + c_)*4u, \
                  Ab + (size_t)(k0_+r_)*NT + t0 + c_); } } \
        _Pragma("unroll") \
        for (int i_ = 0; i_ < (MI > 4 ? 2 : 1); i_++) { int e_ = tid + i_*256; if (e_ < MI*64) { \
            int r_ = e_/(MI*4), c_ = (e_%(MI*4))*4; \
            CPA16(Wsu + (unsigned)((BI)*16*WT + r_*WT + c_)*4u, \
                  Wt + (size_t)(k0_+r_)*M + m0 + c_); } } \
        CPA_COMMIT(); \
    } while (0)

#define EG_XFORM(BI, K0) do { \
        _Pragma("unroll") \
        for (int i_ = 0; i_ < 3; i_++) { int e_ = tid + i_*256; if (e_ < 640) { \
            int r_ = e_/40, c_ = (e_%40)*4; \
            float4 v_ = *(float4*)&As[BI][r_*160 + c_]; \
            float s_ = sc[(K0)+r_], h_ = sh[(K0)+r_]; \
            LRELU4(v_, s_, h_); \
            *(float4*)&As[BI][r_*160 + c_] = v_; } } \
    } while (0)

    EG_LOAD(0, 0);
    EG_LOAD(1, 1);
    CPA_WAIT1();
    __syncthreads();
    EG_XFORM(0, 0);
    __syncthreads();

    for (int kt = 0; kt < KT; kt++) {
        int cb = kt & 1, nb = cb ^ 1;
        const float* An = As[cb];
        const float* Wn = Ws[cb];
        #pragma unroll
        for (int kk = 0; kk < 16; kk++) {
            const ull* arow = (const ull*)&An[kk*160 + tx*10];
            ull ap[5];
            #pragma unroll
            for (int q = 0; q < 5; q++) ap[q] = arow[q];
            float wv[MI];
            #pragma unroll
            for (int h = 0; h < MI; h += 4) {
                float4 wf = *(const float4*)&Wn[kk*WT + ty*MI + h];
                wv[h] = wf.x; wv[h+1] = wf.y; wv[h+2] = wf.z; wv[h+3] = wf.w;
            }
            #pragma unroll
            for (int i = 0; i < MI; i++) {
                ull wp; DUP2(wp, wv[i]);
                #pragma unroll
                for (int q = 0; q < 5; q++) FMA2(acc[i][q], ap[q], wp);
            }
        }
        if (kt + 1 < KT) {
            CPA_WAIT0();
            __syncthreads();
            EG_XFORM(nb, (kt+1) << 4);
            if (kt + 2 < KT) EG_LOAD(kt+2, cb);
            __syncthreads();
        }
    }
#undef EG_LOAD
#undef EG_XFORM

    float* Ob = WRITE ? (Out + (size_t)b*M*NT) : (float*)0;
    #pragma unroll
    for (int i = 0; i < MI; i++) {
        int m = m0 + ty*MI + i;
        float bv = bias[m];
        float sum = 0.f, ss = 0.f, mxv = -INFINITY;
        #pragma unroll
        for (int q = 0; q < 5; q++) {
            float lo, hi;
            UNPK2(lo, hi, acc[i][q]);
            lo += bv; hi += bv;
            if (WRITE)
                *(float2*)(Ob + (size_t)m*NT + t0 + tx*10 + 2*q) = make_float2(lo, hi);
            sum += lo + hi;
            ss = fmaf(lo, lo, ss); ss = fmaf(hi, hi, ss);
            mxv = fmaxf(mxv, fmaxf(lo, hi));
        }
        #pragma unroll
        for (int d = 1; d < 16; d <<= 1) {
            sum += __shfl_xor_sync(0xffffffffu, sum, d);
            ss  += __shfl_xor_sync(0xffffffffu, ss, d);
        }
        if (tx == 0) {
            atomicAdd(&dg_sum[stage][m], (double)sum);
            atomicAdd(&dg_ssq[stage][m], (double)ss);
        }
        float mo = fmaxf(mxv, __shfl_xor_sync(0xffffffffu, mxv, 1));
        if ((tx & 1) == 0)
            dg_z[((size_t)b*512 + zoff + m)*NP + blockIdx.x*8 + (tx >> 1)] = mo;
    }
}

// ====== point-domain SGEMM: FFMA2, cp.async double-buffered (in-place xform),
//        fused stats. Static smem only. ======
template<int MI>
__global__ void __launch_bounds__(256, 2) k_pgemm(
        const float* __restrict__ A, const float* __restrict__ Wt,
        const float* __restrict__ bias,
        const float* __restrict__ sc, const float* __restrict__ sh,
        float* __restrict__ Out, int M, int K, int stage) {
    __shared__ float As[2][16*128];
    __shared__ float Ws[2][16*MI*16];
    const int WT = MI*16;
    unsigned Asu = smem_u32(As);
    unsigned Wsu = smem_u32(Ws);
    int b = blockIdx.z;
    const float* Ab = A + (size_t)b*K*NP;
    float* Ob = Out + (size_t)b*M*NP;
    int m0 = blockIdx.y*WT, t0 = blockIdx.x*128;
    int tid = threadIdx.x, tx = tid & 15, ty = tid >> 4;
    int KT = K >> 4;

    ull acc[MI][4];
    #pragma unroll
    for (int i = 0; i < MI; i++)
        #pragma unroll
        for (int q = 0; q < 4; q++) acc[i][q] = 0ull;

#define PG_LOAD(KT_IDX, BI) do { \
        int k0_ = (KT_IDX) << 4; \
        _Pragma("unroll") \
        for (int i_ = 0; i_ < 2; i_++) { int e_ = tid + i_*256; \
            int r_ = e_ >> 5, c_ = (e_ & 31)*4; \
            CPA16(Asu + (unsigned)((BI)*2048 + r_*128 + c_)*4u, \
                  Ab + (size_t)(k0_+r_)*NP + t0 + c_); } \
        _Pragma("unroll") \
        for (int i_ = 0; i_ < (MI > 4 ? 2 : 1); i_++) { int e_ = tid + i_*256; if (e_ < MI*64) { \
            int r_ = e_/(MI*4), c_ = (e_%(MI*4))*4; \
            CPA16(Wsu + (unsigned)((BI)*16*WT + r_*WT + c_)*4u, \
                  Wt + (size_t)(k0_+r_)*M + m0 + c_); } } \
        CPA_COMMIT(); \
    } while (0)

#define PG_XFORM(BI, K0) do { \
        _Pragma("unroll") \
        for (int i_ = 0; i_ < 2; i_++) { int e_ = tid + i_*256; \
            int r_ = e_ >> 5, c_ = (e_ & 31)*4; \
            float4 v_ = *(float4*)&As[BI][r_*128 + c_]; \
            float s_ = sc[(K0)+r_], h_ = sh[(K0)+r_]; \
            LRELU4(v_, s_, h_); \
            *(float4*)&As[BI][r_*128 + c_] = v_; } \
    } while (0)

    PG_LOAD(0, 0);
    PG_LOAD(1, 1);
    CPA_WAIT1();
    __syncthreads();
    PG_XFORM(0, 0);
    __syncthreads();

    for (int kt = 0; kt < KT; kt++) {
        int cb = kt & 1, nb = cb ^ 1;
        const float* An = As[cb];
        const float* Wn = Ws[cb];
        #pragma unroll
        for (int kk = 0; kk < 16; kk++) {
            const ull* arow = (const ull*)&An[kk*128];
            ull ap[4];
            #pragma unroll
            for (int q = 0; q < 4; q++) ap[q] = arow[tx + 16*q];
            float wv[MI];
            #pragma unroll
            for (int h = 0; h < MI; h += 4) {
                float4 wf = *(const float4*)&Wn[kk*WT + ty*MI + h];
                wv[h] = wf.x; wv[h+1] = wf.y; wv[h+2] = wf.z; wv[h+3] = wf.w;
            }
            #pragma unroll
            for (int i = 0; i < MI; i++) {
                ull wp; DUP2(wp, wv[i]);
                #pragma unroll
                for (int q = 0; q < 4; q++) FMA2(acc[i][q], ap[q], wp);
            }
        }
        if (kt + 1 < KT) {
            CPA_WAIT0();
            __syncthreads();
            PG_XFORM(nb, (kt+1) << 4);
            if (kt + 2 < KT) PG_LOAD(kt+2, cb);
            __syncthreads();
        }
    }
#undef PG_LOAD
#undef PG_XFORM

    #pragma unroll
    for (int i = 0; i < MI; i++) {
        int m = m0 + ty*MI + i;
        float bv = bias[m];
        float sum = 0.f, ss = 0.f;
        #pragma unroll
        for (int q = 0; q < 4; q++) {
            float lo, hi;
            UNPK2(lo, hi, acc[i][q]);
            lo += bv; hi += bv;
            *(float2*)(Ob + (size_t)m*NP + t0 + 2*tx + 32*q) = make_float2(lo, hi);
            sum += lo + hi;
            ss = fmaf(lo, lo, ss); ss = fmaf(hi, hi, ss);
        }
        #pragma unroll
        for (int d = 1; d < 16; d <<= 1) {
            sum += __shfl_xor_sync(0xffffffffu, sum, d);
            ss  += __shfl_xor_sync(0xffffffffu, ss, d);
        }
        if (tx == 0) {
            atomicAdd(&dg_sum[stage][m], (double)sum);
            atomicAdd(&dg_ssq[stage][m], (double)ss);
        }
    }
}

// final bn+lrelu + (B,C,N) -> (B,N,C) transpose
__global__ void k_out(float* __restrict__ out) {
    __shared__ float st[32][33];
    int b = blockIdx.z;
    int c0 = blockIdx.y*32, n0 = blockIdx.x*32;
    int tx = threadIdx.x, ty = threadIdx.y;
    int c = c0 + ty;
    float v = dg_o6[((size_t)b*1024 + c)*NP + n0 + tx];
    v = fmaf(v, dg_sc6[c], dg_sh6[c]);
    st[ty][tx] = v >= 0.f ? v : SLOPE*v;
    __syncthreads();
    out[((size_t)b*NP + n0 + ty)*1024 + c0 + tx] = st[tx][ty];
}

// ---------------- host orchestration ----------------

extern "C" void kernel_launch(void* const* d_in, const int* in_sizes, int n_in,
                              void* d_out, int out_size) {
    (void)in_sizes; (void)n_in; (void)out_size;
    const float* x  = (const float*)d_in[0];
    const float* w1 = (const float*)d_in[1];
    const float* b1 = (const float*)d_in[2];
    const float* g1 = (const float*)d_in[3];
    const float* be1= (const float*)d_in[4];
    const float* w2 = (const float*)d_in[5];
    const float* b2 = (const float*)d_in[6];
    const float* g2 = (const float*)d_in[7];
    const float* be2= (const float*)d_in[8];
    const float* w3 = (const float*)d_in[9];
    const float* b3 = (const float*)d_in[10];
    const float* g3 = (const float*)d_in[11];
    const float* be3= (const float*)d_in[12];
    const float* w4 = (const float*)d_in[13];
    const float* b4 = (const float*)d_in[14];
    const float* g4 = (const float*)d_in[15];
    const float* be4= (const float*)d_in[16];
    const float* w5 = (const float*)d_in[17];
    const float* b5 = (const float*)d_in[18];
    const float* g5 = (const float*)d_in[19];
    const float* be5= (const float*)d_in[20];
    const float* w6 = (const float*)d_in[21];
    const float* b6 = (const float*)d_in[22];
    const float* g6 = (const float*)d_in[23];
    const float* be6= (const float*)d_in[24];

    float *p_h2, *p_h3, *p_z, *p_o5, *p_o6;
    float *p_scZ, *p_shZ, *p_sc5, *p_sh5, *p_sc6, *p_sh6;
    float *p_w2t, *p_w3t, *p_w4t, *p_w5t, *p_w6t;
    cudaGetSymbolAddress((void**)&p_h2, dg_h2);
    cudaGetSymbolAddress((void**)&p_h3, dg_h3);
    cudaGetSymbolAddress((void**)&p_z,  dg_z);
    cudaGetSymbolAddress((void**)&p_o5, dg_o5);
    cudaGetSymbolAddress((void**)&p_o6, dg_o6);
    cudaGetSymbolAddress((void**)&p_scZ, dg_scZ);
    cudaGetSymbolAddress((void**)&p_shZ, dg_shZ);
    cudaGetSymbolAddress((void**)&p_sc5, dg_sc5);
    cudaGetSymbolAddress((void**)&p_sh5, dg_sh5);
    cudaGetSymbolAddress((void**)&p_sc6, dg_sc6);
    cudaGetSymbolAddress((void**)&p_sh6, dg_sh6);
    cudaGetSymbolAddress((void**)&p_w2t, dg_w2t);
    cudaGetSymbolAddress((void**)&p_w3t, dg_w3t);
    cudaGetSymbolAddress((void**)&p_w4t, dg_w4t);
    cudaGetSymbolAddress((void**)&p_w5t, dg_w5t);
    cudaGetSymbolAddress((void**)&p_w6t, dg_w6t);

    const float cntE = (float)(NB*NP*NK);
    const float cntP = (float)(NB*NP);

    k_zero<<<6, 1024>>>();
    k_wt<<<dim3(64/32, 64/32), dim3(32, 32)>>>(w2, p_w2t, 64, 64);
    k_wt<<<dim3(64/32, 128/32), dim3(32, 32)>>>(w3, p_w3t, 128, 64);
    k_wt<<<dim3(128/32, 256/32), dim3(32, 32)>>>(w4, p_w4t, 256, 128);
    k_wt<<<dim3(512/32, 256/32), dim3(32, 32)>>>(w5, p_w5t, 256, 512);
    k_wt<<<dim3(256/32, 1024/32), dim3(32, 32)>>>(w6, p_w6t, 1024, 256);
    k_xx<<<NB, NP>>>(x);
    k_pdist<<<dim3(NP/32, NP/32, NB), dim3(8, 16)>>>(x);
    k_topk<<<NB*NP/8, 256>>>();
    k_ps<<<dim3(NP/256, 64, NB), 256>>>(x, w1);

    // stage-0 stats + max from P/S/idx (no h1 tensor)
    k_h1ns<<<dim3(NP/256, 64, NB), 256>>>(b1);
    k_finalize<<<1, 64>>>(0, 64, cntE, g1, be1, p_scZ, p_shZ);

    // conv2: 64 <- 64, A gathered on the fly
    k_g2<<<dim3(NT/160, 1, NB), 256>>>(p_w2t, b1, b2, p_scZ, p_shZ, p_h2);
    k_finalize<<<1, 64>>>(1, 64, cntE, g2, be2, p_scZ + 64, p_shZ + 64);

    // conv3: 128 <- 64 (MI=8)
    k_egemm<8, true><<<dim3(NT/160, 1, NB), 256>>>(p_h2, p_w3t, b3, p_scZ + 64, p_shZ + 64, p_h3, 128, 64, 2, 128);
    k_finalize<<<1, 128>>>(2, 128, cntE, g3, be3, p_scZ + 128, p_shZ + 128);

    // conv4: 256 <- 128, stats+max only (no output tensor)
    k_egemm<8, false><<<dim3(NT/160, 2, NB), 256>>>(p_h3, p_w4t, b4, p_scZ + 128, p_shZ + 128, (float*)0, 256, 128, 3, 256);
    k_finalize<<<1, 256>>>(3, 256, cntE, g4, be4, p_scZ + 256, p_shZ + 256);

    // conv5: 256 <- 512 over points
    k_pgemm<8><<<dim3(NP/128, 2, NB), 256>>>(p_z, p_w5t, b5, p_scZ, p_shZ, p_o5, 256, 512, 4);
    k_finalize<<<1, 256>>>(4, 256, cntP, g5, be5, p_sc5, p_sh5);

    // conv6: 1024 <- 256
    k_pgemm<8><<<dim3(NP/128, 8, NB), 256>>>(p_o5, p_w6t, b6, p_sc5, p_sh5, p_o6, 1024, 256, 5);
    k_finalize<<<1, 1024>>>(5, 1024, cntP, g6, be6, p_sc6, p_sh6);

    k_out<<<dim3(NP/32, 1024/32, NB), dim3(32, 32)>>>((float*)d_out);
}